// round 3
// baseline (speedup 1.0000x reference)
#include <cuda_runtime.h>

#define NN 50000
#define EE 800000
#define FIN 10
#define HD 64
#define NLAYERS 3

// Scratch (static device globals; no allocation allowed)
__device__ float g_hA[NN * HD];
__device__ float g_hB[NN * HD];
__device__ float g_ew[EE];
__device__ float g_agg[NN * HD];
__device__ float g_cnt[NN];

// ---------------- input projection: h = relu(x @ Wp + bp) ----------------
__global__ void proj_kernel(const float* __restrict__ x, const float* __restrict__ Wp,
                            const float* __restrict__ bp, float* __restrict__ h) {
    int idx = blockIdx.x * blockDim.x + threadIdx.x;
    if (idx >= NN * HD) return;
    int n = idx >> 6, j = idx & 63;
    const float* xr = x + n * FIN;
    float acc = __ldg(bp + j);
#pragma unroll
    for (int k = 0; k < FIN; k++)
        acc = fmaf(__ldg(xr + k), __ldg(Wp + k * HD + j), acc);
    h[idx] = fmaxf(acc, 0.f);
}

// ---------------- edge MLP: ew = sigmoid(relu(ea@w1+b1)@w2+b2) ----------------
__global__ void edge_kernel(const float* __restrict__ ea, const float* __restrict__ w1,
                            const float* __restrict__ b1, const float* __restrict__ w2,
                            const float* __restrict__ b2) {
    __shared__ float s1[48], sb1[16], s2[16], sb2;
    int t = threadIdx.x;
    if (t < 48) s1[t] = w1[t];
    if (t < 16) { sb1[t] = b1[t]; s2[t] = w2[t]; }
    if (t == 0) sb2 = b2[0];
    __syncthreads();
    int e = blockIdx.x * blockDim.x + t;
    if (e >= EE) return;
    float a0 = ea[e * 3 + 0], a1 = ea[e * 3 + 1], a2 = ea[e * 3 + 2];
    float acc = sb2;
#pragma unroll
    for (int j = 0; j < 16; j++) {
        float hj = fmaf(a2, s1[32 + j], fmaf(a1, s1[16 + j], fmaf(a0, s1[j], sb1[j])));
        acc = fmaf(fmaxf(hj, 0.f), s2[j], acc);
    }
    g_ew[e] = 1.f / (1.f + __expf(-acc));
}

// ---------------- zero agg + cnt ----------------
__global__ void zero_kernel() {
    int i = blockIdx.x * blockDim.x + threadIdx.x;
    if (i < NN * HD / 4) reinterpret_cast<float4*>(g_agg)[i] = make_float4(0.f, 0.f, 0.f, 0.f);
    if (i < NN) g_cnt[i] = 0.f;
}

// ---------------- scatter: agg[dst] += h[src]*ew; cnt[dst] += ew ----------------
// 16 lanes per edge; each lane moves one float4 of the 64-wide feature row.
__global__ void scatter_kernel(const float* __restrict__ h, const int* __restrict__ ei) {
    int gid = blockIdx.x * blockDim.x + threadIdx.x;
    int e = gid >> 4;
    if (e >= EE) return;
    int lane16 = threadIdx.x & 15;
    int s = __ldg(ei + e);
    int d = __ldg(ei + EE + e);
    float w = __ldg(g_ew + e);
    float4 m = __ldg(reinterpret_cast<const float4*>(h + (size_t)s * HD) + lane16);
    m.x *= w; m.y *= w; m.z *= w; m.w *= w;
    float* p = g_agg + (size_t)d * HD + lane16 * 4;
    asm volatile("red.global.add.v4.f32 [%0], {%1,%2,%3,%4};"
                 :: "l"(p), "f"(m.x), "f"(m.y), "f"(m.z), "f"(m.w) : "memory");
    if (lane16 == 0) atomicAdd(g_cnt + d, w);
}

// ---------------- node update: h = LN(h + relu([h,agg/cnt] @ nw + nb)) ----------------
// Warp per node. nw transposed into smem with row stride 132 floats -> conflict-free LDS.128.
__global__ void node_kernel(const float* __restrict__ h, const float* __restrict__ nw,
                            const float* __restrict__ nb, const float* __restrict__ lng,
                            const float* __restrict__ lnb, float* __restrict__ hout) {
    __shared__ float sW[64 * 132];
    __shared__ float sv[8][128];
    int tid = threadIdx.x;
    for (int idx = tid; idx < 128 * 64; idx += blockDim.x) {
        int k = idx >> 6, j = idx & 63;
        sW[j * 132 + k] = nw[idx];
    }
    __syncthreads();
    int lane = tid & 31, wrp = tid >> 5;
    int gw = blockIdx.x * 8 + wrp;
    int nwarps = gridDim.x * 8;
    float nb0 = __ldg(nb + lane), nb1 = __ldg(nb + 32 + lane);
    float g0 = __ldg(lng + lane), g1 = __ldg(lng + 32 + lane);
    float b0 = __ldg(lnb + lane), b1 = __ldg(lnb + 32 + lane);
    const float4* w0 = reinterpret_cast<const float4*>(sW + lane * 132);
    const float4* w1 = reinterpret_cast<const float4*>(sW + (lane + 32) * 132);
    float* v = sv[wrp];
    const float4* vf = reinterpret_cast<const float4*>(v);
    for (int n = gw; n < NN; n += nwarps) {
        size_t base = (size_t)n * HD;
        float hv0 = __ldg(h + base + lane), hv1 = __ldg(h + base + 32 + lane);
        float inv = 1.f / fmaxf(g_cnt[n], 1e-12f);
        float a0 = g_agg[base + lane] * inv, a1 = g_agg[base + 32 + lane] * inv;
        v[lane] = hv0; v[32 + lane] = hv1; v[64 + lane] = a0; v[96 + lane] = a1;
        __syncwarp();
        float acc0 = nb0, acc1 = nb1;
#pragma unroll
        for (int k4 = 0; k4 < 32; k4++) {
            float4 vv = vf[k4];
            float4 wa = w0[k4];
            float4 wb = w1[k4];
            acc0 = fmaf(vv.x, wa.x, fmaf(vv.y, wa.y, fmaf(vv.z, wa.z, fmaf(vv.w, wa.w, acc0))));
            acc1 = fmaf(vv.x, wb.x, fmaf(vv.y, wb.y, fmaf(vv.z, wb.z, fmaf(vv.w, wb.w, acc1))));
        }
        float y0 = hv0 + fmaxf(acc0, 0.f);
        float y1 = hv1 + fmaxf(acc1, 0.f);
        float s = y0 + y1;
#pragma unroll
        for (int o = 16; o > 0; o >>= 1) s += __shfl_xor_sync(0xffffffffu, s, o);
        float mu = s * 0.015625f;
        float d0 = y0 - mu, d1 = y1 - mu;
        float q = d0 * d0 + d1 * d1;
#pragma unroll
        for (int o = 16; o > 0; o >>= 1) q += __shfl_xor_sync(0xffffffffu, q, o);
        float rstd = rsqrtf(q * 0.015625f + 1e-5f);
        hout[base + lane] = fmaf(d0 * rstd, g0, b0);
        hout[base + 32 + lane] = fmaf(d1 * rstd, g1, b1);
        __syncwarp();
    }
}

// ---------------- head: out = relu(h @ hw1 + hb1) @ hw2 + hb2 ----------------
// Warp per node; lane = one of 32 hidden units; warp-reduce for final dot.
__global__ void head_kernel(const float* __restrict__ h, const float* __restrict__ hw1,
                            const float* __restrict__ hb1, const float* __restrict__ hw2,
                            const float* __restrict__ hb2, float* __restrict__ out) {
    __shared__ float sW[32 * 76];
    __shared__ float sv[8][64];
    int tid = threadIdx.x;
    for (int idx = tid; idx < 64 * 32; idx += blockDim.x) {
        int k = idx >> 5, j = idx & 31;
        sW[j * 76 + k] = hw1[idx];
    }
    __syncthreads();
    int lane = tid & 31, wrp = tid >> 5;
    int gw = blockIdx.x * 8 + wrp;
    int nwarps = gridDim.x * 8;
    float bb1 = __ldg(hb1 + lane);
    float w2 = __ldg(hw2 + lane);
    float bb2 = __ldg(hb2);
    const float4* wr = reinterpret_cast<const float4*>(sW + lane * 76);
    float* v = sv[wrp];
    const float4* vf = reinterpret_cast<const float4*>(v);
    for (int n = gw; n < NN; n += nwarps) {
        size_t base = (size_t)n * HD;
        v[lane] = __ldg(h + base + lane);
        v[32 + lane] = __ldg(h + base + 32 + lane);
        __syncwarp();
        float acc = bb1;
#pragma unroll
        for (int k4 = 0; k4 < 16; k4++) {
            float4 vv = vf[k4];
            float4 wa = wr[k4];
            acc = fmaf(vv.x, wa.x, fmaf(vv.y, wa.y, fmaf(vv.z, wa.z, fmaf(vv.w, wa.w, acc))));
        }
        float p = fmaxf(acc, 0.f) * w2;
#pragma unroll
        for (int o = 16; o > 0; o >>= 1) p += __shfl_xor_sync(0xffffffffu, p, o);
        if (lane == 0) out[n] = p + bb2;
        __syncwarp();
    }
}

extern "C" void kernel_launch(void* const* d_in, const int* in_sizes, int n_in,
                              void* d_out, int out_size) {
    const float* x   = (const float*)d_in[0];
    const int*   ei  = (const int*)d_in[1];
    const float* ea  = (const float*)d_in[2];
    const float* Wp  = (const float*)d_in[3];
    const float* bp  = (const float*)d_in[4];
    const float* ew1 = (const float*)d_in[5];
    const float* eb1 = (const float*)d_in[6];
    const float* ew2 = (const float*)d_in[7];
    const float* eb2 = (const float*)d_in[8];
    const float* nw  = (const float*)d_in[9];
    const float* nb  = (const float*)d_in[10];
    const float* lng = (const float*)d_in[11];
    const float* lnb = (const float*)d_in[12];
    const float* hw1 = (const float*)d_in[13];
    const float* hb1 = (const float*)d_in[14];
    const float* hw2 = (const float*)d_in[15];
    const float* hb2 = (const float*)d_in[16];
    float* out = (float*)d_out;

    float* hA; cudaGetSymbolAddress((void**)&hA, g_hA);
    float* hB; cudaGetSymbolAddress((void**)&hB, g_hB);

    proj_kernel<<<(NN * HD + 255) / 256, 256>>>(x, Wp, bp, hA);

    float* hin = hA;
    float* hout = hB;
    for (int l = 0; l < NLAYERS; l++) {
        zero_kernel<<<(NN * HD / 4 + 255) / 256, 256>>>();
        edge_kernel<<<(EE + 255) / 256, 256>>>(ea, ew1 + l * 48, eb1 + l * 16,
                                               ew2 + l * 16, eb2 + l);
        scatter_kernel<<<(EE * 16 + 255) / 256, 256>>>(hin, ei);
        node_kernel<<<592, 256>>>(hin, nw + l * 128 * 64, nb + l * 64,
                                  lng + l * 64, lnb + l * 64, hout);
        float* t = hin; hin = hout; hout = t;
    }
    head_kernel<<<592, 256>>>(hin, hw1, hb1, hw2, hb2, out);
}

// round 4
// speedup vs baseline: 1.1661x; 1.1661x over previous
#include <cuda_runtime.h>

#define NN 50000
#define EE 800000
#define FIN 10
#define HD 64
#define NLAYERS 3

// Scratch (static device globals; no allocation allowed)
__device__ float g_hA[NN * HD];
__device__ float g_hB[NN * HD];
__device__ float g_ew[NLAYERS * EE];
__device__ float g_agg[NN * HD];
__device__ int   g_deg[NN];
__device__ int   g_off[NN + 1];
__device__ int   g_cur[NN];
__device__ int2  g_csr[EE];

// ---- packed f32x2 helpers ----
__device__ __forceinline__ unsigned long long pk2(float x, float y) {
    unsigned long long r;
    asm("mov.b64 %0, {%1,%2};" : "=l"(r) : "f"(x), "f"(y));
    return r;
}
__device__ __forceinline__ float hsum2(unsigned long long a) {
    float x, y;
    asm("mov.b64 {%0,%1}, %2;" : "=f"(x), "=f"(y) : "l"(a));
    return x + y;
}
__device__ __forceinline__ void fma2(unsigned long long& d, unsigned long long a,
                                     unsigned long long b) {
    asm("fma.rn.f32x2 %0, %1, %2, %0;" : "+l"(d) : "l"(a), "l"(b));
}

// ---------------- CSR build ----------------
__global__ void zero_deg_kernel() {
    int i = blockIdx.x * blockDim.x + threadIdx.x;
    if (i < NN) g_deg[i] = 0;
}

__global__ void hist_kernel(const int* __restrict__ ei) {
    int e = blockIdx.x * blockDim.x + threadIdx.x;
    if (e < EE) atomicAdd(&g_deg[__ldg(ei + EE + e)], 1);
}

// single-block exclusive scan over 50000 degrees -> g_off, g_cur
__global__ void scan_kernel() {
    __shared__ int ss[1024];
    const int CH = 49;  // 1024*49 = 50176 >= NN
    int t = threadIdx.x;
    int start = t * CH;
    int end = min(start + CH, NN);
    int s = 0;
    for (int i = start; i < end; i++) s += g_deg[i];
    ss[t] = s;
    __syncthreads();
    for (int off = 1; off < 1024; off <<= 1) {
        int v = (t >= off) ? ss[t - off] : 0;
        __syncthreads();
        ss[t] += v;
        __syncthreads();
    }
    int run = (t == 0) ? 0 : ss[t - 1];
    for (int i = start; i < end; i++) {
        g_off[i] = run;
        g_cur[i] = run;
        run += g_deg[i];
    }
    if (t == 1023) g_off[NN] = run;
}

__global__ void fill_kernel(const int* __restrict__ ei) {
    int e = blockIdx.x * blockDim.x + threadIdx.x;
    if (e >= EE) return;
    int s = __ldg(ei + e);
    int d = __ldg(ei + EE + e);
    int pos = atomicAdd(&g_cur[d], 1);
    g_csr[pos] = make_int2(s, e);
}

// ---------------- input projection: h = relu(x @ Wp + bp) ----------------
__global__ void proj_kernel(const float* __restrict__ x, const float* __restrict__ Wp,
                            const float* __restrict__ bp, float* __restrict__ h) {
    int idx = blockIdx.x * blockDim.x + threadIdx.x;
    if (idx >= NN * HD) return;
    int n = idx >> 6, j = idx & 63;
    const float* xr = x + n * FIN;
    float acc = __ldg(bp + j);
#pragma unroll
    for (int k = 0; k < FIN; k++)
        acc = fmaf(__ldg(xr + k), __ldg(Wp + k * HD + j), acc);
    h[idx] = fmaxf(acc, 0.f);
}

// ---------------- edge MLPs for ALL 3 layers in one pass ----------------
__global__ void edge_kernel(const float* __restrict__ ea, const float* __restrict__ ew1,
                            const float* __restrict__ eb1, const float* __restrict__ ew2,
                            const float* __restrict__ eb2) {
    __shared__ float s1[3 * 48], sb1[3 * 16], s2[3 * 16], sb2[3];
    int t = threadIdx.x;
    if (t < 144) s1[t] = ew1[t];
    if (t < 48) { sb1[t] = eb1[t]; s2[t] = ew2[t]; }
    if (t < 3) sb2[t] = eb2[t];
    __syncthreads();
    int e = blockIdx.x * blockDim.x + t;
    if (e >= EE) return;
    float a0 = ea[e * 3 + 0], a1 = ea[e * 3 + 1], a2 = ea[e * 3 + 2];
#pragma unroll
    for (int l = 0; l < 3; l++) {
        const float* w1l = s1 + l * 48;
        const float* b1l = sb1 + l * 16;
        const float* w2l = s2 + l * 16;
        float acc = sb2[l];
#pragma unroll
        for (int j = 0; j < 16; j++) {
            float hj = fmaf(a2, w1l[32 + j], fmaf(a1, w1l[16 + j], fmaf(a0, w1l[j], b1l[j])));
            acc = fmaf(fmaxf(hj, 0.f), w2l[j], acc);
        }
        g_ew[l * EE + e] = 1.f / (1.f + __expf(-acc));
    }
}

// ---------------- gather: agg[n] = (sum_e ew*h[src]) / max(sum_e ew, eps) ----------------
// Warp per node via CSR; plain stores, no atomics, no zero pass.
__global__ void gather_kernel(const float* __restrict__ h, int layer) {
    const float* __restrict__ ewl = g_ew + layer * EE;
    int gw = (blockIdx.x * blockDim.x + threadIdx.x) >> 5;
    int lane = threadIdx.x & 31;
    int nwarps = (gridDim.x * blockDim.x) >> 5;
    for (int n = gw; n < NN; n += nwarps) {
        int beg = g_off[n], end = g_off[n + 1];
        float ax = 0.f, ay = 0.f, bx = 0.f, by = 0.f, swa = 0.f, swb = 0.f;
        int i = beg;
        for (; i + 1 < end; i += 2) {
            int2 sa = __ldg(&g_csr[i]);
            int2 sb = __ldg(&g_csr[i + 1]);
            float wa = __ldg(ewl + sa.y);
            float wb = __ldg(ewl + sb.y);
            float2 ha = __ldg(reinterpret_cast<const float2*>(h + (size_t)sa.x * HD) + lane);
            float2 hb = __ldg(reinterpret_cast<const float2*>(h + (size_t)sb.x * HD) + lane);
            ax = fmaf(wa, ha.x, ax); ay = fmaf(wa, ha.y, ay); swa += wa;
            bx = fmaf(wb, hb.x, bx); by = fmaf(wb, hb.y, by); swb += wb;
        }
        if (i < end) {
            int2 sa = __ldg(&g_csr[i]);
            float wa = __ldg(ewl + sa.y);
            float2 ha = __ldg(reinterpret_cast<const float2*>(h + (size_t)sa.x * HD) + lane);
            ax = fmaf(wa, ha.x, ax); ay = fmaf(wa, ha.y, ay); swa += wa;
        }
        float inv = 1.f / fmaxf(swa + swb, 1e-12f);
        reinterpret_cast<float2*>(g_agg + (size_t)n * HD)[lane] =
            make_float2((ax + bx) * inv, (ay + by) * inv);
    }
}

// ---------------- node update: h = LN(h + relu([h,agg] @ nw + nb)) ----------------
// 4 warps/block, 4 nodes/warp, packed f32x2 FMA. sW transposed, stride 132 (conflict-free).
__global__ void __launch_bounds__(128) node_kernel(
    const float* __restrict__ h, const float* __restrict__ nw,
    const float* __restrict__ nb, const float* __restrict__ lng,
    const float* __restrict__ lnb, float* __restrict__ hout) {
    __shared__ float sW[64 * 132];
    __shared__ float sv[4][4 * 128];
    int tid = threadIdx.x;
    for (int idx = tid; idx < 128 * 64; idx += blockDim.x) {
        int k = idx >> 6, j = idx & 63;
        sW[j * 132 + k] = nw[idx];
    }
    __syncthreads();
    int lane = tid & 31, wrp = tid >> 5;
    int group = blockIdx.x * 4 + wrp;
    int ngroups = gridDim.x * 4;
    float nb0 = __ldg(nb + lane), nb1 = __ldg(nb + 32 + lane);
    float gg0 = __ldg(lng + lane), gg1 = __ldg(lng + 32 + lane);
    float bb0 = __ldg(lnb + lane), bb1 = __ldg(lnb + 32 + lane);
    const ulonglong2* w0p = reinterpret_cast<const ulonglong2*>(sW + lane * 132);
    const ulonglong2* w1p = reinterpret_cast<const ulonglong2*>(sW + (lane + 32) * 132);
    float* v = sv[wrp];
    for (int n0 = group * 4; n0 < NN; n0 += ngroups * 4) {
#pragma unroll
        for (int t = 0; t < 4; t++) {
            size_t base = (size_t)(n0 + t) * HD;
            float2 hv = __ldg(reinterpret_cast<const float2*>(h + base) + lane);
            float2 av = __ldg(reinterpret_cast<const float2*>(g_agg + base) + lane);
            reinterpret_cast<float2*>(v + t * 128)[lane] = hv;
            reinterpret_cast<float2*>(v + t * 128 + 64)[lane] = av;
        }
        __syncwarp();
        unsigned long long a0[4], a1[4];
#pragma unroll
        for (int t = 0; t < 4; t++) { a0[t] = pk2(nb0, 0.f); a1[t] = pk2(nb1, 0.f); }
#pragma unroll 8
        for (int k4 = 0; k4 < 32; k4++) {
            ulonglong2 wa = w0p[k4];
            ulonglong2 wb = w1p[k4];
#pragma unroll
            for (int t = 0; t < 4; t++) {
                ulonglong2 vv = reinterpret_cast<const ulonglong2*>(v + t * 128)[k4];
                fma2(a0[t], vv.x, wa.x); fma2(a0[t], vv.y, wa.y);
                fma2(a1[t], vv.x, wb.x); fma2(a1[t], vv.y, wb.y);
            }
        }
#pragma unroll
        for (int t = 0; t < 4; t++) {
            size_t base = (size_t)(n0 + t) * HD;
            float y0 = v[t * 128 + lane] + fmaxf(hsum2(a0[t]), 0.f);
            float y1 = v[t * 128 + 32 + lane] + fmaxf(hsum2(a1[t]), 0.f);
            float s = y0 + y1;
#pragma unroll
            for (int o = 16; o > 0; o >>= 1) s += __shfl_xor_sync(0xffffffffu, s, o);
            float mu = s * 0.015625f;
            float d0 = y0 - mu, d1 = y1 - mu;
            float q = d0 * d0 + d1 * d1;
#pragma unroll
            for (int o = 16; o > 0; o >>= 1) q += __shfl_xor_sync(0xffffffffu, q, o);
            float rstd = rsqrtf(q * 0.015625f + 1e-5f);
            hout[base + lane] = fmaf(d0 * rstd, gg0, bb0);
            hout[base + 32 + lane] = fmaf(d1 * rstd, gg1, bb1);
        }
        __syncwarp();
    }
}

// ---------------- head: out = relu(h @ hw1 + hb1) @ hw2 + hb2 ----------------
// 4 warps/block, 4 nodes/warp, lane = hidden unit (32), f32x2.
__global__ void __launch_bounds__(128) head_kernel(
    const float* __restrict__ h, const float* __restrict__ hw1,
    const float* __restrict__ hb1, const float* __restrict__ hw2,
    const float* __restrict__ hb2, float* __restrict__ out) {
    __shared__ float sW[32 * 68];
    __shared__ float sv[4][4 * 64];
    int tid = threadIdx.x;
    for (int idx = tid; idx < 64 * 32; idx += blockDim.x) {
        int k = idx >> 5, j = idx & 31;
        sW[j * 68 + k] = hw1[idx];
    }
    __syncthreads();
    int lane = tid & 31, wrp = tid >> 5;
    int group = blockIdx.x * 4 + wrp;
    int ngroups = gridDim.x * 4;
    float bb1 = __ldg(hb1 + lane);
    float w2 = __ldg(hw2 + lane);
    float bb2 = __ldg(hb2);
    const ulonglong2* wp = reinterpret_cast<const ulonglong2*>(sW + lane * 68);
    float* v = sv[wrp];
    for (int n0 = group * 4; n0 < NN; n0 += ngroups * 4) {
#pragma unroll
        for (int t = 0; t < 4; t++) {
            size_t base = (size_t)(n0 + t) * HD;
            reinterpret_cast<float2*>(v + t * 64)[lane] =
                __ldg(reinterpret_cast<const float2*>(h + base) + lane);
        }
        __syncwarp();
        unsigned long long acc[4];
#pragma unroll
        for (int t = 0; t < 4; t++) acc[t] = pk2(bb1, 0.f);
#pragma unroll
        for (int k4 = 0; k4 < 16; k4++) {
            ulonglong2 w = wp[k4];
#pragma unroll
            for (int t = 0; t < 4; t++) {
                ulonglong2 vv = reinterpret_cast<const ulonglong2*>(v + t * 64)[k4];
                fma2(acc[t], vv.x, w.x); fma2(acc[t], vv.y, w.y);
            }
        }
#pragma unroll
        for (int t = 0; t < 4; t++) {
            float p = fmaxf(hsum2(acc[t]), 0.f) * w2;
#pragma unroll
            for (int o = 16; o > 0; o >>= 1) p += __shfl_xor_sync(0xffffffffu, p, o);
            if (lane == 0) out[n0 + t] = p + bb2;
        }
        __syncwarp();
    }
}

extern "C" void kernel_launch(void* const* d_in, const int* in_sizes, int n_in,
                              void* d_out, int out_size) {
    const float* x   = (const float*)d_in[0];
    const int*   ei  = (const int*)d_in[1];
    const float* ea  = (const float*)d_in[2];
    const float* Wp  = (const float*)d_in[3];
    const float* bp  = (const float*)d_in[4];
    const float* ew1 = (const float*)d_in[5];
    const float* eb1 = (const float*)d_in[6];
    const float* ew2 = (const float*)d_in[7];
    const float* eb2 = (const float*)d_in[8];
    const float* nw  = (const float*)d_in[9];
    const float* nb  = (const float*)d_in[10];
    const float* lng = (const float*)d_in[11];
    const float* lnb = (const float*)d_in[12];
    const float* hw1 = (const float*)d_in[13];
    const float* hb1 = (const float*)d_in[14];
    const float* hw2 = (const float*)d_in[15];
    const float* hb2 = (const float*)d_in[16];
    float* out = (float*)d_out;

    float* hA; cudaGetSymbolAddress((void**)&hA, g_hA);
    float* hB; cudaGetSymbolAddress((void**)&hB, g_hB);

    // CSR build (edge_index is the same every call; rebuilt deterministically per call)
    zero_deg_kernel<<<(NN + 255) / 256, 256>>>();
    hist_kernel<<<(EE + 255) / 256, 256>>>(ei);
    scan_kernel<<<1, 1024>>>();
    fill_kernel<<<(EE + 255) / 256, 256>>>(ei);

    proj_kernel<<<(NN * HD + 255) / 256, 256>>>(x, Wp, bp, hA);
    edge_kernel<<<(EE + 255) / 256, 256>>>(ea, ew1, eb1, ew2, eb2);

    float* hin = hA;
    float* hout = hB;
    for (int l = 0; l < NLAYERS; l++) {
        gather_kernel<<<6250, 256>>>(hin, l);
        node_kernel<<<740, 128>>>(hin, nw + l * 128 * 64, nb + l * 64,
                                  lng + l * 64, lnb + l * 64, hout);
        float* t = hin; hin = hout; hout = t;
    }
    head_kernel<<<296, 128>>>(hin, hw1, hb1, hw2, hb2, out);
}

// round 5
// speedup vs baseline: 1.2819x; 1.0993x over previous
#include <cuda_runtime.h>

#define NN 50000
#define EE 800000
#define FIN 10
#define HD 64
#define NLAYERS 3
#define SCAN_BLOCKS 49

// Scratch (static device globals; no allocation allowed)
__device__ float g_hA[NN * HD];
__device__ float g_hB[NN * HD];
__device__ float g_ews[NLAYERS * EE];   // edge weights, CSR-sorted per layer
__device__ float g_agg[NN * HD];
__device__ int   g_deg[NN];
__device__ int   g_off[NN + 1];
__device__ int   g_cur[NN];
__device__ int   g_src[EE];             // CSR: source node per slot
__device__ int   g_pos[EE];             // edge id -> CSR slot
__device__ int   g_scanflag[SCAN_BLOCKS + 1];
__device__ int   g_scanpre[SCAN_BLOCKS + 1];

// ---- packed f32x2 helpers ----
__device__ __forceinline__ unsigned long long pk2(float x, float y) {
    unsigned long long r;
    asm("mov.b64 %0, {%1,%2};" : "=l"(r) : "f"(x), "f"(y));
    return r;
}
__device__ __forceinline__ float hsum2(unsigned long long a) {
    float x, y;
    asm("mov.b64 {%0,%1}, %2;" : "=f"(x), "=f"(y) : "l"(a));
    return x + y;
}
__device__ __forceinline__ void fma2(unsigned long long& d, unsigned long long a,
                                     unsigned long long b) {
    asm("fma.rn.f32x2 %0, %1, %2, %0;" : "+l"(d) : "l"(a), "l"(b));
}

// ---------------- input projection: h = relu(x @ Wp + bp) ----------------
__global__ void proj_kernel(const float* __restrict__ x, const float* __restrict__ Wp,
                            const float* __restrict__ bp, float* __restrict__ h) {
    int idx = blockIdx.x * blockDim.x + threadIdx.x;
    if (idx >= NN * HD) return;
    int n = idx >> 6, j = idx & 63;
    const float* xr = x + n * FIN;
    float acc = __ldg(bp + j);
#pragma unroll
    for (int k = 0; k < FIN; k++)
        acc = fmaf(__ldg(xr + k), __ldg(Wp + k * HD + j), acc);
    h[idx] = fmaxf(acc, 0.f);
}

// ---------------- degree histogram ----------------
__global__ void hist_kernel(const int* __restrict__ ei) {
    int e = blockIdx.x * blockDim.x + threadIdx.x;
    if (e < EE) atomicAdd(&g_deg[__ldg(ei + EE + e)], 1);
}

// ---------------- decoupled-lookback exclusive scan of degrees ----------------
// 49 blocks x 1024 threads (all resident -> chain cannot deadlock).
__global__ void __launch_bounds__(1024) scan_kernel() {
    __shared__ int s[1024];
    __shared__ int s_pre;
    int b = blockIdx.x, t = threadIdx.x;
    int i = b * 1024 + t;
    int v = (i < NN) ? g_deg[i] : 0;
    s[t] = v;
    __syncthreads();
#pragma unroll
    for (int off = 1; off < 1024; off <<= 1) {
        int x = (t >= off) ? s[t - off] : 0;
        __syncthreads();
        s[t] += x;
        __syncthreads();
    }
    int agg = s[1023];
    if (t == 0) {
        int pre = 0;
        if (b > 0) {
            while (((volatile int*)g_scanflag)[b] == 0) __nanosleep(20);
            __threadfence();
            pre = g_scanpre[b];
        }
        g_scanpre[b + 1] = pre + agg;
        __threadfence();
        ((volatile int*)g_scanflag)[b + 1] = 1;
        s_pre = pre;
        if (b == SCAN_BLOCKS - 1) g_off[NN] = pre + agg;
    }
    __syncthreads();
    int excl = s_pre + s[t] - v;
    if (i < NN) { g_off[i] = excl; g_cur[i] = excl; }
}

// ---------------- CSR fill: slot per edge + src; record pos for ew sorting ----------------
__global__ void fill_kernel(const int* __restrict__ ei) {
    int e = blockIdx.x * blockDim.x + threadIdx.x;
    if (e >= EE) return;
    int s = __ldg(ei + e);
    int d = __ldg(ei + EE + e);
    int pos = atomicAdd(&g_cur[d], 1);
    g_src[pos] = s;
    g_pos[e] = pos;
}

// ---------------- edge MLPs for ALL 3 layers, written CSR-sorted ----------------
__global__ void edge_kernel(const float* __restrict__ ea, const float* __restrict__ ew1,
                            const float* __restrict__ eb1, const float* __restrict__ ew2,
                            const float* __restrict__ eb2) {
    __shared__ float s1[3 * 48], sb1[3 * 16], s2[3 * 16], sb2[3];
    __shared__ float sea[256 * 3];
    int t = threadIdx.x;
    if (t < 144) s1[t] = ew1[t];
    if (t < 48) { sb1[t] = eb1[t]; s2[t] = ew2[t]; }
    if (t < 3) sb2[t] = eb2[t];
    int base = blockIdx.x * 256 * 3;  // EE % 256 == 0, no guard needed
#pragma unroll
    for (int idx = t; idx < 768; idx += 256) sea[idx] = ea[base + idx];
    __syncthreads();
    int e = blockIdx.x * blockDim.x + t;
    float a0 = sea[t * 3], a1 = sea[t * 3 + 1], a2 = sea[t * 3 + 2];
    int p = __ldg(g_pos + e);
#pragma unroll
    for (int l = 0; l < 3; l++) {
        const float* w1l = s1 + l * 48;
        const float* b1l = sb1 + l * 16;
        const float* w2l = s2 + l * 16;
        float acc = sb2[l];
#pragma unroll
        for (int j = 0; j < 16; j++) {
            float hj = fmaf(a2, w1l[32 + j], fmaf(a1, w1l[16 + j], fmaf(a0, w1l[j], b1l[j])));
            acc = fmaf(fmaxf(hj, 0.f), w2l[j], acc);
        }
        g_ews[l * EE + p] = 1.f / (1.f + __expf(-acc));
    }
}

// ---------------- gather: agg[n] = (sum ew*h[src]) / max(sum ew, eps) ----------------
// Warp per node; src + ew read contiguously from CSR-sorted arrays; 4-way unroll.
__global__ void gather_kernel(const float* __restrict__ h, int layer) {
    const float* __restrict__ ewl = g_ews + layer * EE;
    int gw = (blockIdx.x * blockDim.x + threadIdx.x) >> 5;
    int lane = threadIdx.x & 31;
    int nwarps = (gridDim.x * blockDim.x) >> 5;
    for (int n = gw; n < NN; n += nwarps) {
        int beg = g_off[n], end = g_off[n + 1];
        float ax = 0.f, ay = 0.f, bx = 0.f, by = 0.f, sw = 0.f;
        int i = beg;
        for (; i + 3 < end; i += 4) {
            int s0 = __ldg(g_src + i), s1 = __ldg(g_src + i + 1);
            int s2 = __ldg(g_src + i + 2), s3 = __ldg(g_src + i + 3);
            float w0 = __ldg(ewl + i), w1 = __ldg(ewl + i + 1);
            float w2 = __ldg(ewl + i + 2), w3 = __ldg(ewl + i + 3);
            float2 h0 = __ldg(reinterpret_cast<const float2*>(h + (size_t)s0 * HD) + lane);
            float2 h1 = __ldg(reinterpret_cast<const float2*>(h + (size_t)s1 * HD) + lane);
            float2 h2 = __ldg(reinterpret_cast<const float2*>(h + (size_t)s2 * HD) + lane);
            float2 h3 = __ldg(reinterpret_cast<const float2*>(h + (size_t)s3 * HD) + lane);
            ax = fmaf(w0, h0.x, ax); ay = fmaf(w0, h0.y, ay);
            bx = fmaf(w1, h1.x, bx); by = fmaf(w1, h1.y, by);
            ax = fmaf(w2, h2.x, ax); ay = fmaf(w2, h2.y, ay);
            bx = fmaf(w3, h3.x, bx); by = fmaf(w3, h3.y, by);
            sw += (w0 + w1) + (w2 + w3);
        }
        for (; i < end; i++) {
            int s0 = __ldg(g_src + i);
            float w0 = __ldg(ewl + i);
            float2 h0 = __ldg(reinterpret_cast<const float2*>(h + (size_t)s0 * HD) + lane);
            ax = fmaf(w0, h0.x, ax); ay = fmaf(w0, h0.y, ay);
            sw += w0;
        }
        float inv = 1.f / fmaxf(sw, 1e-12f);
        reinterpret_cast<float2*>(g_agg + (size_t)n * HD)[lane] =
            make_float2((ax + bx) * inv, (ay + by) * inv);
    }
}

// ---------------- node update: h = LN(h + relu([h,agg] @ nw + nb)) ----------------
// 8 warps/block (shared weight tile), 4 nodes/warp, packed f32x2 FMA.
__global__ void __launch_bounds__(256) node_kernel(
    const float* __restrict__ h, const float* __restrict__ nw,
    const float* __restrict__ nb, const float* __restrict__ lng,
    const float* __restrict__ lnb, float* __restrict__ hout) {
    __shared__ float sW[64 * 132];
    __shared__ float sv[8][4 * 128];
    int tid = threadIdx.x;
    for (int idx = tid; idx < 128 * 64; idx += blockDim.x) {
        int k = idx >> 6, j = idx & 63;
        sW[j * 132 + k] = nw[idx];
    }
    __syncthreads();
    int lane = tid & 31, wrp = tid >> 5;
    int group = blockIdx.x * 8 + wrp;
    int ngroups = gridDim.x * 8;
    float nb0 = __ldg(nb + lane), nb1 = __ldg(nb + 32 + lane);
    float gg0 = __ldg(lng + lane), gg1 = __ldg(lng + 32 + lane);
    float bb0 = __ldg(lnb + lane), bb1 = __ldg(lnb + 32 + lane);
    const ulonglong2* w0p = reinterpret_cast<const ulonglong2*>(sW + lane * 132);
    const ulonglong2* w1p = reinterpret_cast<const ulonglong2*>(sW + (lane + 32) * 132);
    float* v = sv[wrp];
    for (int n0 = group * 4; n0 < NN; n0 += ngroups * 4) {
#pragma unroll
        for (int t = 0; t < 4; t++) {
            size_t base = (size_t)(n0 + t) * HD;
            float2 hv = __ldg(reinterpret_cast<const float2*>(h + base) + lane);
            float2 av = __ldg(reinterpret_cast<const float2*>(g_agg + base) + lane);
            reinterpret_cast<float2*>(v + t * 128)[lane] = hv;
            reinterpret_cast<float2*>(v + t * 128 + 64)[lane] = av;
        }
        __syncwarp();
        unsigned long long a0[4], a1[4];
#pragma unroll
        for (int t = 0; t < 4; t++) { a0[t] = pk2(nb0, 0.f); a1[t] = pk2(nb1, 0.f); }
#pragma unroll 8
        for (int k4 = 0; k4 < 32; k4++) {
            ulonglong2 wa = w0p[k4];
            ulonglong2 wb = w1p[k4];
#pragma unroll
            for (int t = 0; t < 4; t++) {
                ulonglong2 vv = reinterpret_cast<const ulonglong2*>(v + t * 128)[k4];
                fma2(a0[t], vv.x, wa.x); fma2(a0[t], vv.y, wa.y);
                fma2(a1[t], vv.x, wb.x); fma2(a1[t], vv.y, wb.y);
            }
        }
#pragma unroll
        for (int t = 0; t < 4; t++) {
            size_t base = (size_t)(n0 + t) * HD;
            float y0 = v[t * 128 + lane] + fmaxf(hsum2(a0[t]), 0.f);
            float y1 = v[t * 128 + 32 + lane] + fmaxf(hsum2(a1[t]), 0.f);
            float s = y0 + y1;
#pragma unroll
            for (int o = 16; o > 0; o >>= 1) s += __shfl_xor_sync(0xffffffffu, s, o);
            float mu = s * 0.015625f;
            float d0 = y0 - mu, d1 = y1 - mu;
            float q = d0 * d0 + d1 * d1;
#pragma unroll
            for (int o = 16; o > 0; o >>= 1) q += __shfl_xor_sync(0xffffffffu, q, o);
            float rstd = rsqrtf(q * 0.015625f + 1e-5f);
            hout[base + lane] = fmaf(d0 * rstd, gg0, bb0);
            hout[base + 32 + lane] = fmaf(d1 * rstd, gg1, bb1);
        }
        __syncwarp();
    }
}

// ---------------- head: out = relu(h @ hw1 + hb1) @ hw2 + hb2 ----------------
__global__ void __launch_bounds__(128) head_kernel(
    const float* __restrict__ h, const float* __restrict__ hw1,
    const float* __restrict__ hb1, const float* __restrict__ hw2,
    const float* __restrict__ hb2, float* __restrict__ out) {
    __shared__ float sW[32 * 68];
    __shared__ float sv[4][4 * 64];
    int tid = threadIdx.x;
    for (int idx = tid; idx < 64 * 32; idx += blockDim.x) {
        int k = idx >> 5, j = idx & 31;
        sW[j * 68 + k] = hw1[idx];
    }
    __syncthreads();
    int lane = tid & 31, wrp = tid >> 5;
    int group = blockIdx.x * 4 + wrp;
    int ngroups = gridDim.x * 4;
    float bb1 = __ldg(hb1 + lane);
    float w2 = __ldg(hw2 + lane);
    float bb2 = __ldg(hb2);
    const ulonglong2* wp = reinterpret_cast<const ulonglong2*>(sW + lane * 68);
    float* v = sv[wrp];
    for (int n0 = group * 4; n0 < NN; n0 += ngroups * 4) {
#pragma unroll
        for (int t = 0; t < 4; t++) {
            size_t base = (size_t)(n0 + t) * HD;
            reinterpret_cast<float2*>(v + t * 64)[lane] =
                __ldg(reinterpret_cast<const float2*>(h + base) + lane);
        }
        __syncwarp();
        unsigned long long acc[4];
#pragma unroll
        for (int t = 0; t < 4; t++) acc[t] = pk2(bb1, 0.f);
#pragma unroll
        for (int k4 = 0; k4 < 16; k4++) {
            ulonglong2 w = wp[k4];
#pragma unroll
            for (int t = 0; t < 4; t++) {
                ulonglong2 vv = reinterpret_cast<const ulonglong2*>(v + t * 64)[k4];
                fma2(acc[t], vv.x, w.x); fma2(acc[t], vv.y, w.y);
            }
        }
#pragma unroll
        for (int t = 0; t < 4; t++) {
            float p = fmaxf(hsum2(acc[t]), 0.f) * w2;
#pragma unroll
            for (int o = 16; o > 0; o >>= 1) p += __shfl_xor_sync(0xffffffffu, p, o);
            if (lane == 0) out[n0 + t] = p + bb2;
        }
        __syncwarp();
    }
}

extern "C" void kernel_launch(void* const* d_in, const int* in_sizes, int n_in,
                              void* d_out, int out_size) {
    const float* x   = (const float*)d_in[0];
    const int*   ei  = (const int*)d_in[1];
    const float* ea  = (const float*)d_in[2];
    const float* Wp  = (const float*)d_in[3];
    const float* bp  = (const float*)d_in[4];
    const float* ew1 = (const float*)d_in[5];
    const float* eb1 = (const float*)d_in[6];
    const float* ew2 = (const float*)d_in[7];
    const float* eb2 = (const float*)d_in[8];
    const float* nw  = (const float*)d_in[9];
    const float* nb  = (const float*)d_in[10];
    const float* lng = (const float*)d_in[11];
    const float* lnb = (const float*)d_in[12];
    const float* hw1 = (const float*)d_in[13];
    const float* hb1 = (const float*)d_in[14];
    const float* hw2 = (const float*)d_in[15];
    const float* hb2 = (const float*)d_in[16];
    float* out = (float*)d_out;

    float* hA; cudaGetSymbolAddress((void**)&hA, g_hA);
    float* hB; cudaGetSymbolAddress((void**)&hB, g_hB);
    void* degp;  cudaGetSymbolAddress(&degp, g_deg);
    void* flagp; cudaGetSymbolAddress(&flagp, g_scanflag);

    // zero degree counters + lookback flags via graph memset nodes
    cudaMemsetAsync(degp, 0, NN * sizeof(int));
    cudaMemsetAsync(flagp, 0, (SCAN_BLOCKS + 1) * sizeof(int));

    proj_kernel<<<(NN * HD + 255) / 256, 256>>>(x, Wp, bp, hA);   // (1)
    hist_kernel<<<(EE + 255) / 256, 256>>>(ei);                   // (2)
    scan_kernel<<<SCAN_BLOCKS, 1024>>>();                         // (3)
    fill_kernel<<<(EE + 255) / 256, 256>>>(ei);                   // (4)
    edge_kernel<<<EE / 256, 256>>>(ea, ew1, eb1, ew2, eb2);       // (5)

    float* hin = hA;
    float* hout = hB;
    for (int l = 0; l < NLAYERS; l++) {
        gather_kernel<<<6250, 256>>>(hin, l);                     // (6) <- ncu -s 5 lands here
        node_kernel<<<(NN + 31) / 32, 256>>>(hin, nw + l * 128 * 64, nb + l * 64,
                                             lng + l * 64, lnb + l * 64, hout);
        float* t = hin; hin = hout; hout = t;
    }
    head_kernel<<<296, 128>>>(hin, hw1, hb1, hw2, hb2, out);
}